// round 1
// baseline (speedup 1.0000x reference)
#include <cuda_runtime.h>
#include <cstdint>

// ---------------- scratch (device globals; no allocation allowed) ----------
__device__ float g_q[4096 * 2048];   // Q after proj+rope   [B*S][H*DH]
__device__ float g_k[4096 * 512];    // K after proj+rope   [B*S][HKV*DH]
__device__ float g_v[4096 * 512];    // V after proj        [B*S][HKV*DH]
__device__ float g_o[4096 * 2048];   // attention output    [B*S][H*DH]

// ---------------- packed f32x2 helpers -------------------------------------
__device__ __forceinline__ unsigned long long pack2(float lo, float hi) {
    unsigned long long r;
    asm("mov.b64 %0,{%1,%2};" : "=l"(r) : "f"(lo), "f"(hi));
    return r;
}
__device__ __forceinline__ void unpack2(unsigned long long v, float& lo, float& hi) {
    asm("mov.b64 {%0,%1},%2;" : "=f"(lo), "=f"(hi) : "l"(v));
}
__device__ __forceinline__ unsigned long long fma2(unsigned long long a,
                                                   unsigned long long b,
                                                   unsigned long long c) {
    unsigned long long d;
    asm("fma.rn.f32x2 %0,%1,%2,%3;" : "=l"(d) : "l"(a), "l"(b), "l"(c));
    return d;
}

// ---------------- GEMM: C[M,N] = A[M,K] @ B[K,N], fp32, f32x2 inner --------
#define BM 128
#define BN 128
#define BK 16

__global__ __launch_bounds__(256, 2) void gemm_f32x2(
    const float* __restrict__ A, const float* __restrict__ B,
    float* __restrict__ C, int M, int N, int K) {
    __shared__ __align__(16) unsigned long long As2[BK * BM];  // (a,a) packed
    __shared__ __align__(16) float Bs[BK * BN];

    const int t  = threadIdx.x;
    const int tx = t & 15;       // N direction, 8 cols each
    const int ty = t >> 4;       // M direction, 8 rows each
    const int bm = blockIdx.y * BM;
    const int bn = blockIdx.x * BN;

    unsigned long long acc[8][4];
#pragma unroll
    for (int i = 0; i < 8; i++)
#pragma unroll
        for (int j = 0; j < 4; j++) acc[i][j] = 0ULL;

    for (int k0 = 0; k0 < K; k0 += BK) {
        // load A tile (128 x 16), store transposed + duplicated as (a,a)
#pragma unroll
        for (int l = 0; l < 2; l++) {
            int fi  = t + l * 256;            // 0..511 float4 index
            int row = fi >> 2;
            int c4  = (fi & 3) << 2;
            float4 av = *(const float4*)(A + (size_t)(bm + row) * K + (k0 + c4));
            As2[(c4 + 0) * BM + row] = pack2(av.x, av.x);
            As2[(c4 + 1) * BM + row] = pack2(av.y, av.y);
            As2[(c4 + 2) * BM + row] = pack2(av.z, av.z);
            As2[(c4 + 3) * BM + row] = pack2(av.w, av.w);
        }
        // load B tile (16 x 128)
#pragma unroll
        for (int l = 0; l < 2; l++) {
            int fi  = t + l * 256;
            int row = fi >> 5;
            int c4  = (fi & 31) << 2;
            *(float4*)&Bs[row * BN + c4] =
                *(const float4*)(B + (size_t)(k0 + row) * N + bn + c4);
        }
        __syncthreads();

#pragma unroll
        for (int k = 0; k < BK; k++) {
            ulonglong2 a0 = *(const ulonglong2*)&As2[k * BM + ty * 8 + 0];
            ulonglong2 a1 = *(const ulonglong2*)&As2[k * BM + ty * 8 + 2];
            ulonglong2 a2 = *(const ulonglong2*)&As2[k * BM + ty * 8 + 4];
            ulonglong2 a3 = *(const ulonglong2*)&As2[k * BM + ty * 8 + 6];
            ulonglong2 b0 = *(const ulonglong2*)&Bs[k * BN + tx * 8 + 0];
            ulonglong2 b1 = *(const ulonglong2*)&Bs[k * BN + tx * 8 + 4];
            unsigned long long aa[8] = {a0.x, a0.y, a1.x, a1.y,
                                        a2.x, a2.y, a3.x, a3.y};
            unsigned long long bb[4] = {b0.x, b0.y, b1.x, b1.y};
#pragma unroll
            for (int i = 0; i < 8; i++)
#pragma unroll
                for (int j = 0; j < 4; j++)
                    acc[i][j] = fma2(aa[i], bb[j], acc[i][j]);
        }
        __syncthreads();
    }

#pragma unroll
    for (int i = 0; i < 8; i++) {
        float o0, o1, o2, o3, o4, o5, o6, o7;
        unpack2(acc[i][0], o0, o1);
        unpack2(acc[i][1], o2, o3);
        unpack2(acc[i][2], o4, o5);
        unpack2(acc[i][3], o6, o7);
        float* cp = C + (size_t)(bm + ty * 8 + i) * N + bn + tx * 8;
        *(float4*)cp       = make_float4(o0, o1, o2, o3);
        *(float4*)(cp + 4) = make_float4(o4, o5, o6, o7);
    }
}

// ---------------- RoPE: in-place on g_q, g_k -------------------------------
// One thread per (b*s, d) pair, d in [0,64); loops over all 20 heads.
__global__ void rope_kernel(float* __restrict__ q, float* __restrict__ k,
                            const int* __restrict__ pos_ids) {
    int idx = blockIdx.x * 256 + threadIdx.x;  // B*S*64 = 262144 threads
    int d   = idx & 63;
    int bs  = idx >> 6;  // 0..4095
    int pos = pos_ids[bs];

    // inv_freq = 10000^(-d/64); double path keeps angle error ~1e-14
    double invf = exp((double)d * -0.14391156831212787);  // -ln(10000)/64
    double ang  = (double)pos * invf;
    double r    = ang * 0.15915494309189535;  // / 2pi
    r -= floor(r);
    float th = (float)(r * 6.283185307179586);
    float sn, cs;
    sincosf(th, &sn, &cs);

    float* qp = q + (size_t)bs * 2048 + d;
#pragma unroll
    for (int hh = 0; hh < 16; hh++) {
        float x1 = qp[hh * 128];
        float x2 = qp[hh * 128 + 64];
        qp[hh * 128]      = x1 * cs - x2 * sn;
        qp[hh * 128 + 64] = x2 * cs + x1 * sn;
    }
    float* kp = k + (size_t)bs * 512 + d;
#pragma unroll
    for (int hh = 0; hh < 4; hh++) {
        float x1 = kp[hh * 128];
        float x2 = kp[hh * 128 + 64];
        kp[hh * 128]      = x1 * cs - x2 * sn;
        kp[hh * 128 + 64] = x2 * cs + x1 * sn;
    }
}

// ---------------- causal flash attention, fp32 -----------------------------
// grid: (S/64 q-tiles, H, B); block 256 threads (16x16).
// Thread (ty,tx): score tile rows 4ty..4ty+3, cols 4tx..4tx+3;
//                 O tile rows 4ty..4ty+3, cols 8tx..8tx+7.
#define FS   2048
#define QPAD 129  // stride pad: kills the 16-way conflict of K^T reads

__global__ __launch_bounds__(256, 1) void flash_kernel(
    const float* __restrict__ qb, const float* __restrict__ kb,
    const float* __restrict__ vb, float* __restrict__ ob) {
    extern __shared__ float fsm[];
    float* Qs = fsm;               // 64 x 129
    float* Ks = Qs + 64 * QPAD;    // 64 x 129
    float* Vs = Ks + 64 * QPAD;    // 64 x 128
    float* Ps = Vs + 64 * 128;     // 64 x 65

    const int t  = threadIdx.x;
    const int tx = t & 15;
    const int ty = t >> 4;
    const int qt = (int)gridDim.x - 1 - (int)blockIdx.x;  // heavy tiles first
    const int h  = blockIdx.y;
    const int b  = blockIdx.z;
    const int kvh = h >> 2;  // N_REP = 4
    const int q0 = qt * 64;
    const float scale = 0.08838834764831845f;  // 1/sqrt(128), folded into Q

    // load Q tile, pre-scaled
#pragma unroll
    for (int l = 0; l < 8; l++) {
        int fi = t + l * 256;
        int r  = fi >> 5;
        int c  = (fi & 31) << 2;
        float4 v = *(const float4*)(qb + (size_t)(b * FS + q0 + r) * 2048 + h * 128 + c);
        float* dst = &Qs[r * QPAD + c];
        dst[0] = v.x * scale; dst[1] = v.y * scale;
        dst[2] = v.z * scale; dst[3] = v.w * scale;
    }

    float m[4], lsum[4], o[4][8];
#pragma unroll
    for (int i = 0; i < 4; i++) {
        m[i] = -1e30f; lsum[i] = 0.f;
#pragma unroll
        for (int c = 0; c < 8; c++) o[i][c] = 0.f;
    }

    for (int kt = 0; kt <= qt; kt++) {
        int k0 = kt * 64;
        __syncthreads();  // protects Qs(first iter)/Ks/Vs/Ps reuse
#pragma unroll
        for (int l = 0; l < 8; l++) {
            int fi = t + l * 256;
            int r  = fi >> 5;
            int c  = (fi & 31) << 2;
            size_t goff = (size_t)(b * FS + k0 + r) * 512 + kvh * 128 + c;
            float4 kv = *(const float4*)(kb + goff);
            float* kd = &Ks[r * QPAD + c];
            kd[0] = kv.x; kd[1] = kv.y; kd[2] = kv.z; kd[3] = kv.w;
            *(float4*)&Vs[r * 128 + c] = *(const float4*)(vb + goff);
        }
        __syncthreads();

        // S = Q @ K^T
        float s[4][4];
#pragma unroll
        for (int i = 0; i < 4; i++)
#pragma unroll
            for (int j = 0; j < 4; j++) s[i][j] = 0.f;

#pragma unroll 4
        for (int d = 0; d < 128; d++) {
            float qr[4], kc[4];
#pragma unroll
            for (int i = 0; i < 4; i++) qr[i] = Qs[(ty * 4 + i) * QPAD + d];
#pragma unroll
            for (int j = 0; j < 4; j++) kc[j] = Ks[(tx * 4 + j) * QPAD + d];
#pragma unroll
            for (int i = 0; i < 4; i++)
#pragma unroll
                for (int j = 0; j < 4; j++) s[i][j] += qr[i] * kc[j];
        }

        if (kt == qt) {  // diagonal tile: causal mask (k0 == q0 here)
#pragma unroll
            for (int i = 0; i < 4; i++)
#pragma unroll
                for (int j = 0; j < 4; j++)
                    if (tx * 4 + j > ty * 4 + i) s[i][j] = -1e30f;
        }

        // online softmax (rows shared across the 16 tx lanes of a half-warp)
#pragma unroll
        for (int i = 0; i < 4; i++) {
            float rm = fmaxf(fmaxf(s[i][0], s[i][1]), fmaxf(s[i][2], s[i][3]));
#pragma unroll
            for (int off = 1; off < 16; off <<= 1)
                rm = fmaxf(rm, __shfl_xor_sync(0xffffffffu, rm, off));
            float mn    = fmaxf(m[i], rm);
            float alpha = __expf(m[i] - mn);
            m[i] = mn;
            float rs = 0.f;
#pragma unroll
            for (int j = 0; j < 4; j++) {
                s[i][j] = __expf(s[i][j] - mn);
                rs += s[i][j];
            }
#pragma unroll
            for (int off = 1; off < 16; off <<= 1)
                rs += __shfl_xor_sync(0xffffffffu, rs, off);
            lsum[i] = lsum[i] * alpha + rs;
#pragma unroll
            for (int c = 0; c < 8; c++) o[i][c] *= alpha;
        }

        // stage P to smem for the P@V GEMM
#pragma unroll
        for (int i = 0; i < 4; i++)
#pragma unroll
            for (int j = 0; j < 4; j++)
                Ps[(ty * 4 + i) * 65 + tx * 4 + j] = s[i][j];
        __syncthreads();

        // O += P @ V
#pragma unroll 2
        for (int j = 0; j < 64; j++) {
            float4 v0 = *(const float4*)&Vs[j * 128 + tx * 8];
            float4 v1 = *(const float4*)&Vs[j * 128 + tx * 8 + 4];
#pragma unroll
            for (int i = 0; i < 4; i++) {
                float p = Ps[(ty * 4 + i) * 65 + j];
                o[i][0] += p * v0.x; o[i][1] += p * v0.y;
                o[i][2] += p * v0.z; o[i][3] += p * v0.w;
                o[i][4] += p * v1.x; o[i][5] += p * v1.y;
                o[i][6] += p * v1.z; o[i][7] += p * v1.w;
            }
        }
    }

    // epilogue: normalize + write [B,S,H*DH]
#pragma unroll
    for (int i = 0; i < 4; i++) {
        float inv = 1.0f / lsum[i];
        int r = q0 + ty * 4 + i;
        float* op = ob + (size_t)(b * FS + r) * 2048 + h * 128 + tx * 8;
        *(float4*)op       = make_float4(o[i][0] * inv, o[i][1] * inv,
                                         o[i][2] * inv, o[i][3] * inv);
        *(float4*)(op + 4) = make_float4(o[i][4] * inv, o[i][5] * inv,
                                         o[i][6] * inv, o[i][7] * inv);
    }
}

// ---------------- launch ---------------------------------------------------
extern "C" void kernel_launch(void* const* d_in, const int* in_sizes, int n_in,
                              void* d_out, int out_size) {
    const float* x   = (const float*)d_in[0];
    const int*   pos = (const int*)d_in[1];
    const float* wq  = (const float*)d_in[2];
    const float* wk  = (const float*)d_in[3];
    const float* wv  = (const float*)d_in[4];
    const float* wo  = (const float*)d_in[5];
    float* out = (float*)d_out;

    float *qb, *kb, *vb, *ob;
    cudaGetSymbolAddress((void**)&qb, g_q);
    cudaGetSymbolAddress((void**)&kb, g_k);
    cudaGetSymbolAddress((void**)&vb, g_v);
    cudaGetSymbolAddress((void**)&ob, g_o);

    const int flash_smem = (64 * QPAD * 2 + 64 * 128 + 64 * 65) * 4;  // ~113 KB
    cudaFuncSetAttribute(flash_kernel,
                         cudaFuncAttributeMaxDynamicSharedMemorySize, flash_smem);

    // QKV projections
    gemm_f32x2<<<dim3(16, 32), 256>>>(x, wq, qb, 4096, 2048, 2048);
    gemm_f32x2<<<dim3(4, 32), 256>>>(x, wk, kb, 4096, 512, 2048);
    gemm_f32x2<<<dim3(4, 32), 256>>>(x, wv, vb, 4096, 512, 2048);
    // RoPE (in place on q, k)
    rope_kernel<<<1024, 256>>>(qb, kb, pos);
    // causal flash attention
    flash_kernel<<<dim3(32, 16, 2), 256, flash_smem>>>(qb, kb, vb, ob);
    // output projection -> d_out
    gemm_f32x2<<<dim3(16, 32), 256>>>(ob, wo, out, 4096, 2048, 2048);
}